// round 1
// baseline (speedup 1.0000x reference)
#include <cuda_runtime.h>
#include <cstdint>

#define NN 50000
#define EE 800000
#define CC 64
#define BN_EPS 1e-5f

// ---------------- scratch (static __device__ globals; no allocation) ----------------
static __device__ __align__(16) float g_P[NN * CC];      // x @ W0[:64]
static __device__ __align__(16) float g_Q[NN * CC];      // x @ W0[64:]
static __device__ __align__(16) float g_Y[EE * CC];      // y1 scratch (pre-BN layer1 output)
static __device__ float g_cnt[NN];                       // dst degree (float)
static __device__ int   g_src[EE];
static __device__ int   g_dst[EE];
static __device__ __align__(16) float g_sum[3][CC];
static __device__ __align__(16) float g_sq[3][CC];
static __device__ __align__(16) float g_bnA[3][CC];      // g * rsqrt(var+eps)
static __device__ __align__(16) float g_bnB[3][CC];      // beta - mean*A
static __device__ int   g_is64;

// ---------------- kernels ----------------

__global__ void k_zero(float* __restrict__ out_nodes) {
    int i = blockIdx.x * 256 + threadIdx.x;
    if (i < NN * CC) out_nodes[i] = 0.0f;
    if (i < NN) g_cnt[i] = 0.0f;
    if (i < 3 * CC) {
        ((float*)g_sum)[i] = 0.0f;
        ((float*)g_sq)[i] = 0.0f;
    }
}

// Detect whether edge_index is int64 (odd 32-bit words all zero) or int32.
__global__ void k_detect(const unsigned* __restrict__ w) {
    __shared__ int bad;
    if (threadIdx.x == 0) bad = 0;
    __syncthreads();
    int b = 0;
    for (int i = threadIdx.x; i < 1024; i += 256)
        if (w[2 * i + 1] != 0u) b = 1;
    if (b) atomicOr(&bad, 1);
    __syncthreads();
    if (threadIdx.x == 0) g_is64 = bad ? 0 : 1;
}

__global__ void k_convert(const void* __restrict__ ei) {
    int e = blockIdx.x * 256 + threadIdx.x;
    if (e >= EE) return;
    int s, d;
    if (g_is64) {
        const long long* p = (const long long*)ei;
        s = (int)p[e];
        d = (int)p[EE + e];
    } else {
        const int* p = (const int*)ei;
        s = p[e];
        d = p[EE + e];
    }
    g_src[e] = s;
    g_dst[e] = d;
}

// Node-level GEMM: P = x @ W0[:64], Q = x @ W0[64:].  Tile: 32 nodes x 128 cols per block.
__global__ void __launch_bounds__(256) k_node(const float* __restrict__ x,
                                              const float* __restrict__ W0) {
    __shared__ float sW[64][128];   // cols 0..63 = W0a, 64..127 = W0b
    __shared__ float sx[32][64];
    int t = threadIdx.x;
#pragma unroll
    for (int i = 0; i < 32; i++) {
        int idx = t + i * 256;      // 0..8191
        int k = idx >> 7;
        int cc = idx & 127;
        sW[k][cc] = (cc < 64) ? W0[k * 64 + cc] : W0[(64 + k) * 64 + (cc - 64)];
    }
    int n0 = blockIdx.x * 32;
#pragma unroll
    for (int i = 0; i < 8; i++) {
        int idx = t + i * 256;      // 0..2047
        int nl = idx >> 6;
        int k = idx & 63;
        int n = n0 + nl;
        sx[nl][k] = (n < NN) ? x[n * 64 + k] : 0.0f;
    }
    __syncthreads();
    int tc = t & 31;                // 4 cols each -> 128 cols
    int tn = t >> 5;                // 4 nodes each -> 32 nodes
    float acc[4][4] = {};
#pragma unroll 16
    for (int k = 0; k < 64; k++) {
        float4 w = *(const float4*)&sW[k][tc * 4];
        float x0 = sx[tn * 4 + 0][k];
        float x1 = sx[tn * 4 + 1][k];
        float x2 = sx[tn * 4 + 2][k];
        float x3 = sx[tn * 4 + 3][k];
        acc[0][0] = fmaf(x0, w.x, acc[0][0]); acc[0][1] = fmaf(x0, w.y, acc[0][1]);
        acc[0][2] = fmaf(x0, w.z, acc[0][2]); acc[0][3] = fmaf(x0, w.w, acc[0][3]);
        acc[1][0] = fmaf(x1, w.x, acc[1][0]); acc[1][1] = fmaf(x1, w.y, acc[1][1]);
        acc[1][2] = fmaf(x1, w.z, acc[1][2]); acc[1][3] = fmaf(x1, w.w, acc[1][3]);
        acc[2][0] = fmaf(x2, w.x, acc[2][0]); acc[2][1] = fmaf(x2, w.y, acc[2][1]);
        acc[2][2] = fmaf(x2, w.z, acc[2][2]); acc[2][3] = fmaf(x2, w.w, acc[2][3]);
        acc[3][0] = fmaf(x3, w.x, acc[3][0]); acc[3][1] = fmaf(x3, w.y, acc[3][1]);
        acc[3][2] = fmaf(x3, w.z, acc[3][2]); acc[3][3] = fmaf(x3, w.w, acc[3][3]);
    }
#pragma unroll
    for (int i = 0; i < 4; i++) {
        int n = n0 + tn * 4 + i;
        if (n < NN) {
            float4 v = make_float4(acc[i][0], acc[i][1], acc[i][2], acc[i][3]);
            if (tc < 16)
                *(float4*)&g_P[n * 64 + tc * 4] = v;
            else
                *(float4*)&g_Q[n * 64 + (tc - 16) * 4] = v;
        }
    }
}

// Layer-0 stats: per-column sum/sumsq of y0 = P[dst]+Q[src]; also dst degree counts.
__global__ void k_stats0() {
    __shared__ float ss[CC], sq[CC];
    int t = threadIdx.x;
    if (t < CC) { ss[t] = 0.0f; sq[t] = 0.0f; }
    __syncthreads();
    int lane = t & 31;
    int warp = (blockIdx.x * 256 + t) >> 5;
    int nw = (gridDim.x * 256) >> 5;
    float2 s = make_float2(0.0f, 0.0f), q = make_float2(0.0f, 0.0f);
    for (int e = warp; e < EE; e += nw) {
        int dst = g_dst[e], src = g_src[e];
        float2 p = *(const float2*)&g_P[dst * CC + 2 * lane];
        float2 qq = *(const float2*)&g_Q[src * CC + 2 * lane];
        float y0 = p.x + qq.x, y1 = p.y + qq.y;
        s.x += y0; s.y += y1;
        q.x = fmaf(y0, y0, q.x); q.y = fmaf(y1, y1, q.y);
        if (lane == 0) atomicAdd(&g_cnt[dst], 1.0f);
    }
    atomicAdd(&ss[2 * lane], s.x);
    atomicAdd(&ss[2 * lane + 1], s.y);
    atomicAdd(&sq[2 * lane], q.x);
    atomicAdd(&sq[2 * lane + 1], q.y);
    __syncthreads();
    if (t < CC) {
        atomicAdd(&g_sum[0][t], ss[t]);
        atomicAdd(&g_sq[0][t], sq[t]);
    }
}

__global__ void k_finalize(int layer, const float* __restrict__ gam,
                           const float* __restrict__ bet) {
    int c = threadIdx.x;
    float inv = 1.0f / (float)EE;
    float m = g_sum[layer][c] * inv;
    float v = g_sq[layer][c] * inv - m * m;
    float a = gam[c] * rsqrtf(v + BN_EPS);
    g_bnA[layer][c] = a;
    g_bnB[layer][c] = bet[c] - m * a;
}

// Layer 1: per 64-edge tile: gather P[dst]+Q[src], BN0+ReLU -> Ht (transposed smem),
// GEMM with W1 -> y1 to g_Y, accumulate stats1.
__global__ void __launch_bounds__(256) k_layer1(const float* __restrict__ W1) {
    __shared__ float Ht[CC][68];
    __shared__ float Ws[CC][CC];
    __shared__ float ssum[CC], ssq[CC];
    int t = threadIdx.x;
#pragma unroll
    for (int i = 0; i < 16; i++)
        ((float*)Ws)[t + i * 256] = W1[t + i * 256];
    if (t < CC) { ssum[t] = 0.0f; ssq[t] = 0.0f; }

    int e0 = blockIdx.x * 64;
    int le = t & 63, half = t >> 6;
    int e = e0 + le;
    int dst = g_dst[e], src = g_src[e];
    const float4* Pp = (const float4*)&g_P[dst * CC + half * 16];
    const float4* Qp = (const float4*)&g_Q[src * CC + half * 16];
#pragma unroll
    for (int i = 0; i < 4; i++) {
        float4 p = Pp[i], qv = Qp[i];
        int c = half * 16 + i * 4;
        float4 A = *(const float4*)&g_bnA[0][c];
        float4 B = *(const float4*)&g_bnB[0][c];
        Ht[c + 0][le] = fmaxf(fmaf(A.x, p.x + qv.x, B.x), 0.0f);
        Ht[c + 1][le] = fmaxf(fmaf(A.y, p.y + qv.y, B.y), 0.0f);
        Ht[c + 2][le] = fmaxf(fmaf(A.z, p.z + qv.z, B.z), 0.0f);
        Ht[c + 3][le] = fmaxf(fmaf(A.w, p.w + qv.w, B.w), 0.0f);
    }
    __syncthreads();

    int te = t & 15, tc = t >> 4;
    float acc[4][4] = {};
#pragma unroll 16
    for (int k = 0; k < CC; k++) {
        float4 h = *(const float4*)&Ht[k][te * 4];
        float4 w = *(const float4*)&Ws[k][tc * 4];
        acc[0][0] = fmaf(h.x, w.x, acc[0][0]); acc[0][1] = fmaf(h.x, w.y, acc[0][1]);
        acc[0][2] = fmaf(h.x, w.z, acc[0][2]); acc[0][3] = fmaf(h.x, w.w, acc[0][3]);
        acc[1][0] = fmaf(h.y, w.x, acc[1][0]); acc[1][1] = fmaf(h.y, w.y, acc[1][1]);
        acc[1][2] = fmaf(h.y, w.z, acc[1][2]); acc[1][3] = fmaf(h.y, w.w, acc[1][3]);
        acc[2][0] = fmaf(h.z, w.x, acc[2][0]); acc[2][1] = fmaf(h.z, w.y, acc[2][1]);
        acc[2][2] = fmaf(h.z, w.z, acc[2][2]); acc[2][3] = fmaf(h.z, w.w, acc[2][3]);
        acc[3][0] = fmaf(h.w, w.x, acc[3][0]); acc[3][1] = fmaf(h.w, w.y, acc[3][1]);
        acc[3][2] = fmaf(h.w, w.z, acc[3][2]); acc[3][3] = fmaf(h.w, w.w, acc[3][3]);
    }
#pragma unroll
    for (int i = 0; i < 4; i++) {
        int ee2 = e0 + te * 4 + i;
        *(float4*)&g_Y[ee2 * CC + tc * 4] =
            make_float4(acc[i][0], acc[i][1], acc[i][2], acc[i][3]);
    }
    float ps[4], pq[4];
#pragma unroll
    for (int j = 0; j < 4; j++) {
        ps[j] = acc[0][j] + acc[1][j] + acc[2][j] + acc[3][j];
        pq[j] = acc[0][j] * acc[0][j] + acc[1][j] * acc[1][j] +
                acc[2][j] * acc[2][j] + acc[3][j] * acc[3][j];
    }
#pragma unroll
    for (int off = 8; off > 0; off >>= 1) {
#pragma unroll
        for (int j = 0; j < 4; j++) {
            ps[j] += __shfl_down_sync(0xffffffffu, ps[j], off, 16);
            pq[j] += __shfl_down_sync(0xffffffffu, pq[j], off, 16);
        }
    }
    if (te == 0) {
#pragma unroll
        for (int j = 0; j < 4; j++) {
            atomicAdd(&ssum[tc * 4 + j], ps[j]);
            atomicAdd(&ssq[tc * 4 + j], pq[j]);
        }
    }
    __syncthreads();
    if (t < CC) {
        atomicAdd(&g_sum[1][t], ssum[t]);
        atomicAdd(&g_sq[1][t], ssq[t]);
    }
}

// Layer 2: read y1, BN1+ReLU -> Ht, GEMM with W2 -> y2 into d_out edge region, stats2.
__global__ void __launch_bounds__(256) k_layer2(const float* __restrict__ W2,
                                                float* __restrict__ outE) {
    __shared__ float Ht[CC][68];
    __shared__ float Ws[CC][CC];
    __shared__ float ssum[CC], ssq[CC];
    int t = threadIdx.x;
#pragma unroll
    for (int i = 0; i < 16; i++)
        ((float*)Ws)[t + i * 256] = W2[t + i * 256];
    if (t < CC) { ssum[t] = 0.0f; ssq[t] = 0.0f; }

    int e0 = blockIdx.x * 64;
    int cfix = t & 63;
    float A = g_bnA[1][cfix], Bb = g_bnB[1][cfix];
#pragma unroll
    for (int j = 0; j < 16; j++) {
        int idx = t + j * 256;
        int lel = (t >> 6) + j * 4;
        float v = g_Y[e0 * CC + idx];
        Ht[cfix][lel] = fmaxf(fmaf(A, v, Bb), 0.0f);
    }
    __syncthreads();

    int te = t & 15, tc = t >> 4;
    float acc[4][4] = {};
#pragma unroll 16
    for (int k = 0; k < CC; k++) {
        float4 h = *(const float4*)&Ht[k][te * 4];
        float4 w = *(const float4*)&Ws[k][tc * 4];
        acc[0][0] = fmaf(h.x, w.x, acc[0][0]); acc[0][1] = fmaf(h.x, w.y, acc[0][1]);
        acc[0][2] = fmaf(h.x, w.z, acc[0][2]); acc[0][3] = fmaf(h.x, w.w, acc[0][3]);
        acc[1][0] = fmaf(h.y, w.x, acc[1][0]); acc[1][1] = fmaf(h.y, w.y, acc[1][1]);
        acc[1][2] = fmaf(h.y, w.z, acc[1][2]); acc[1][3] = fmaf(h.y, w.w, acc[1][3]);
        acc[2][0] = fmaf(h.z, w.x, acc[2][0]); acc[2][1] = fmaf(h.z, w.y, acc[2][1]);
        acc[2][2] = fmaf(h.z, w.z, acc[2][2]); acc[2][3] = fmaf(h.z, w.w, acc[2][3]);
        acc[3][0] = fmaf(h.w, w.x, acc[3][0]); acc[3][1] = fmaf(h.w, w.y, acc[3][1]);
        acc[3][2] = fmaf(h.w, w.z, acc[3][2]); acc[3][3] = fmaf(h.w, w.w, acc[3][3]);
    }
#pragma unroll
    for (int i = 0; i < 4; i++) {
        int ee2 = e0 + te * 4 + i;
        *(float4*)&outE[ee2 * CC + tc * 4] =
            make_float4(acc[i][0], acc[i][1], acc[i][2], acc[i][3]);
    }
    float ps[4], pq[4];
#pragma unroll
    for (int j = 0; j < 4; j++) {
        ps[j] = acc[0][j] + acc[1][j] + acc[2][j] + acc[3][j];
        pq[j] = acc[0][j] * acc[0][j] + acc[1][j] * acc[1][j] +
                acc[2][j] * acc[2][j] + acc[3][j] * acc[3][j];
    }
#pragma unroll
    for (int off = 8; off > 0; off >>= 1) {
#pragma unroll
        for (int j = 0; j < 4; j++) {
            ps[j] += __shfl_down_sync(0xffffffffu, ps[j], off, 16);
            pq[j] += __shfl_down_sync(0xffffffffu, pq[j], off, 16);
        }
    }
    if (te == 0) {
#pragma unroll
        for (int j = 0; j < 4; j++) {
            atomicAdd(&ssum[tc * 4 + j], ps[j]);
            atomicAdd(&ssq[tc * 4 + j], pq[j]);
        }
    }
    __syncthreads();
    if (t < CC) {
        atomicAdd(&g_sum[2][t], ssum[t]);
        atomicAdd(&g_sq[2][t], ssq[t]);
    }
}

// BN2 + ReLU in place on edge activations, then atomic scatter-add into node sums.
__global__ void k_scatter(float* __restrict__ out) {
    int i = blockIdx.x * 256 + threadIdx.x;
    if (i >= EE * 16) return;
    int e = i >> 4, q = i & 15;
    float* oe = out + NN * CC;
    float4 v = *(float4*)&oe[e * CC + q * 4];
    float4 A = *(const float4*)&g_bnA[2][q * 4];
    float4 B = *(const float4*)&g_bnB[2][q * 4];
    v.x = fmaxf(fmaf(A.x, v.x, B.x), 0.0f);
    v.y = fmaxf(fmaf(A.y, v.y, B.y), 0.0f);
    v.z = fmaxf(fmaf(A.z, v.z, B.z), 0.0f);
    v.w = fmaxf(fmaf(A.w, v.w, B.w), 0.0f);
    *(float4*)&oe[e * CC + q * 4] = v;
    int dst = g_dst[e];
    float* a = out + dst * CC + q * 4;
    atomicAdd(a + 0, v.x);
    atomicAdd(a + 1, v.y);
    atomicAdd(a + 2, v.z);
    atomicAdd(a + 3, v.w);
}

__global__ void k_div(float* __restrict__ out) {
    int i = blockIdx.x * 256 + threadIdx.x;
    if (i < NN * CC) {
        float c = g_cnt[i >> 6];
        out[i] = out[i] / fmaxf(c, 1.0f);
    }
}

extern "C" void kernel_launch(void* const* d_in, const int* in_sizes, int n_in,
                              void* d_out, int out_size) {
    const float* x = (const float*)d_in[0];
    const void* ei = d_in[1];
    const float* W0 = (const float*)d_in[2];
    const float* g0 = (const float*)d_in[4];
    const float* be0 = (const float*)d_in[5];
    const float* W1 = (const float*)d_in[6];
    const float* g1 = (const float*)d_in[8];
    const float* be1 = (const float*)d_in[9];
    const float* W2 = (const float*)d_in[10];
    const float* g2 = (const float*)d_in[12];
    const float* be2 = (const float*)d_in[13];
    float* out = (float*)d_out;
    float* outE = out + NN * CC;

    k_zero<<<(NN * CC + 255) / 256, 256>>>(out);
    k_detect<<<1, 256>>>((const unsigned*)ei);
    k_convert<<<(EE + 255) / 256, 256>>>(ei);
    k_node<<<(NN + 31) / 32, 256>>>(x, W0);
    k_stats0<<<2048, 256>>>();
    k_finalize<<<1, 64>>>(0, g0, be0);
    k_layer1<<<EE / 64, 256>>>(W1);
    k_finalize<<<1, 64>>>(1, g1, be1);
    k_layer2<<<EE / 64, 256>>>(W2, outE);
    k_finalize<<<1, 64>>>(2, g2, be2);
    k_scatter<<<(EE * 16 + 255) / 256, 256>>>(out);
    k_div<<<(NN * CC + 255) / 256, 256>>>(out);
}